// round 5
// baseline (speedup 1.0000x reference)
#include <cuda_runtime.h>
#include <cuda_bf16.h>
#include <stdint.h>

#define NN   4096
#define EE   65536
#define OC   200
#define KPAD 256    // padded K for GEMM2
#define NCAT 512    // padded N for GEMM1 weight concat

// ---------------------------------------------------------------------------
// Scratch (device globals; no runtime allocation allowed)
// ---------------------------------------------------------------------------
__device__ __align__(16) __nv_bfloat16 g_xhi[(size_t)NN * NN];   // 32 MB
__device__ __align__(16) __nv_bfloat16 g_xlo[(size_t)NN * NN];   // 32 MB
__device__ __align__(16) __nv_bfloat16 g_w1hi[NCAT * NN];        // [n,k] = Wcat[k,n]
__device__ __align__(16) __nv_bfloat16 g_w1lo[NCAT * NN];
__device__ __align__(16) float g_h[NN * OC];
__device__ __align__(16) float g_z[NN * OC];
__device__ __align__(16) __nv_bfloat16 g_zhi[NN * KPAD];         // relu(z) split, K-padded
__device__ __align__(16) __nv_bfloat16 g_zlo[NN * KPAD];
__device__ __align__(16) __nv_bfloat16 g_wdhi[NN * KPAD];        // [n,k] = W_dec[k,n], padded
__device__ __align__(16) __nv_bfloat16 g_wdlo[NN * KPAD];

// ---------------------------------------------------------------------------
// PTX helpers (sm_100 baseline target: ldmatrix + mma.sync)
// ---------------------------------------------------------------------------
__device__ __forceinline__ uint32_t smem_u32(const void* p) {
    uint32_t a;
    asm("{ .reg .u64 t; cvta.to.shared.u64 t, %1; cvt.u32.u64 %0, t; }" : "=r"(a) : "l"(p));
    return a;
}
#define CP16(sa, gp)  asm volatile("cp.async.cg.shared.global [%0], [%1], 16;" :: "r"(sa), "l"(gp))
#define CP_COMMIT()   asm volatile("cp.async.commit_group;" ::: "memory")
#define CP_WAIT(n)    asm volatile("cp.async.wait_group %0;" :: "n"(n) : "memory")

__device__ __forceinline__ void ldsm_x4(uint32_t* r, uint32_t addr) {
    asm volatile("ldmatrix.sync.aligned.m8n8.x4.shared.b16 {%0,%1,%2,%3}, [%4];"
                 : "=r"(r[0]), "=r"(r[1]), "=r"(r[2]), "=r"(r[3]) : "r"(addr));
}
__device__ __forceinline__ void ldsm_x2(uint32_t* r, uint32_t addr) {
    asm volatile("ldmatrix.sync.aligned.m8n8.x2.shared.b16 {%0,%1}, [%2];"
                 : "=r"(r[0]), "=r"(r[1]) : "r"(addr));
}
__device__ __forceinline__ void mma16816(float* d, const uint32_t* a, const uint32_t* b) {
    asm volatile("mma.sync.aligned.m16n8k16.row.col.f32.bf16.bf16.f32 "
                 "{%0,%1,%2,%3}, {%4,%5,%6,%7}, {%8,%9}, {%0,%1,%2,%3};"
                 : "+f"(d[0]), "+f"(d[1]), "+f"(d[2]), "+f"(d[3])
                 : "r"(a[0]), "r"(a[1]), "r"(a[2]), "r"(a[3]), "r"(b[0]), "r"(b[1]));
}

// SW128-style swizzle for 128-byte rows
__device__ __forceinline__ uint32_t tile_addr(uint32_t base, int row, int kbyte) {
    uint32_t off = row * 128 + kbyte;
    return base + (off ^ ((off >> 3) & 0x70));
}

// SMEM: 3 stages x 4 tiles (Ahi, Alo, Bhi, Blo) x 16KB (128 rows x 128B)
#define TILE_B     16384
#define BUF_B      (4 * TILE_B)          // 64 KB per stage
#define NSTAGE     3
#define SMEM_TOTAL (NSTAGE * BUF_B)      // 196608

// Fill one 128-row x 64-col bf16 tile (swizzled), 256 threads, 4x16B each.
__device__ __forceinline__ void fill_tile(uint32_t sbase, const __nv_bfloat16* __restrict__ gsrc,
                                          int row0, int stride, int k0) {
    const int tid = threadIdx.x;
    #pragma unroll
    for (int t = 0; t < 4; t++) {
        const int q = tid + t * 256;              // 0..1023 16B chunks
        const int r = q >> 3;
        const int c16 = q & 7;
        uint32_t off = r * 128 + c16 * 16;
        uint32_t sw = off ^ ((off >> 3) & 0x70);
        const void* gp = gsrc + (size_t)(row0 + r) * stride + k0 + c16 * 8;
        CP16(sbase + sw, gp);
    }
}

__device__ __forceinline__ void fill_stage(uint32_t sbase, int k0,
    const __nv_bfloat16* Ahi, const __nv_bfloat16* Alo, int arow0, int astride,
    const __nv_bfloat16* Bhi, const __nv_bfloat16* Blo, int brow0, int bstride)
{
    fill_tile(sbase + 0 * TILE_B, Ahi, arow0, astride, k0);
    fill_tile(sbase + 1 * TILE_B, Alo, arow0, astride, k0);
    fill_tile(sbase + 2 * TILE_B, Bhi, brow0, bstride, k0);
    fill_tile(sbase + 3 * TILE_B, Blo, brow0, bstride, k0);
}

// ---------------------------------------------------------------------------
// Merged preprocessing kernel
// ---------------------------------------------------------------------------
__device__ __forceinline__ void split2(float v, __nv_bfloat16& h, __nv_bfloat16& l) {
    h = __float2bfloat16(v);
    l = __float2bfloat16(v - __bfloat162float(h));
}

__global__ __launch_bounds__(256) void conv_pre_kernel(
    const float* __restrict__ x,
    const float* __restrict__ W_rel, const float* __restrict__ W_root,
    const float* __restrict__ W_dec)
{
    const int bid = blockIdx.x;
    if (bid < 16384) {
        const size_t i = ((size_t)bid * 256 + threadIdx.x) * 4;
        float4 v = *reinterpret_cast<const float4*>(x + i);
        __nv_bfloat16 h0, h1, h2, h3, l0, l1, l2, l3;
        split2(v.x, h0, l0); split2(v.y, h1, l1); split2(v.z, h2, l2); split2(v.w, h3, l3);
        *reinterpret_cast<__nv_bfloat162*>(g_xhi + i)     = __nv_bfloat162(h0, h1);
        *reinterpret_cast<__nv_bfloat162*>(g_xhi + i + 2) = __nv_bfloat162(h2, h3);
        *reinterpret_cast<__nv_bfloat162*>(g_xlo + i)     = __nv_bfloat162(l0, l1);
        *reinterpret_cast<__nv_bfloat162*>(g_xlo + i + 2) = __nv_bfloat162(l2, l3);
    } else if (bid < 24576) {
        const int idx = (bid - 16384) * 256 + threadIdx.x;   // n*4096 + k, n<512
        const int n = idx >> 12, k = idx & 4095;
        float v = 0.f;
        if (n < OC)          v = W_rel[k * OC + n];
        else if (n < 2 * OC) v = W_root[k * OC + (n - OC)];
        __nv_bfloat16 h, l; split2(v, h, l);
        g_w1hi[idx] = h; g_w1lo[idx] = l;
    } else {
        const int idx = (bid - 24576) * 256 + threadIdx.x;   // n*256 + k
        const int n = idx >> 8, k = idx & 255;
        float v = (k < OC) ? W_dec[(size_t)k * NN + n] : 0.f;
        __nv_bfloat16 h, l; split2(v, h, l);
        g_wdhi[idx] = h; g_wdlo[idx] = l;
    }
}

// relu(z) split, 8 elems/thread; only cols < 208 are ever consumed by gemm2.
__global__ __launch_bounds__(256) void conv_z_kernel() {
    const int idx = blockIdx.x * 256 + threadIdx.x;
    const int m = idx >> 5;
    const int kk = (idx & 31) * 8;
    if (kk >= 208) return;                 // [208,256) never read by gemm2 MMAs
    __nv_bfloat162 h[4], l[4];
    if (kk < OC) {
        const float4 v0 = *reinterpret_cast<const float4*>(&g_z[m * OC + kk]);
        const float4 v1 = *reinterpret_cast<const float4*>(&g_z[m * OC + kk + 4]);
        float f[8] = {v0.x, v0.y, v0.z, v0.w, v1.x, v1.y, v1.z, v1.w};
        #pragma unroll
        for (int t = 0; t < 4; t++) {
            __nv_bfloat16 h0, h1, l0, l1;
            split2(fmaxf(f[2 * t], 0.f), h0, l0);
            split2(fmaxf(f[2 * t + 1], 0.f), h1, l1);
            h[t] = __nv_bfloat162(h0, h1);
            l[t] = __nv_bfloat162(l0, l1);
        }
    } else {
        #pragma unroll
        for (int t = 0; t < 4; t++) {
            h[t] = __nv_bfloat162(__float2bfloat16(0.f), __float2bfloat16(0.f));
            l[t] = h[t];
        }
    }
    #pragma unroll
    for (int t = 0; t < 4; t++) {
        *reinterpret_cast<__nv_bfloat162*>(g_zhi + m * KPAD + kk + 2 * t) = h[t];
        *reinterpret_cast<__nv_bfloat162*>(g_zlo + m * KPAD + kk + 2 * t) = l[t];
    }
}

// ---------------------------------------------------------------------------
// Edge scatter: g_z[dst] += g_h[src] * w
// ---------------------------------------------------------------------------
__global__ __launch_bounds__(256) void scatter_kernel(const int* __restrict__ ei,
                                                      const float* __restrict__ ew) {
    const int warp = (blockIdx.x * 256 + threadIdx.x) >> 5;
    const int lane = threadIdx.x & 31;
    if (warp >= EE) return;
    const int src = ei[warp];
    const int dst = ei[EE + warp];
    const float w = ew[warp];
    const float4* hs = reinterpret_cast<const float4*>(&g_h[src * OC]);
    float4* zd = reinterpret_cast<float4*>(&g_z[dst * OC]);
    #pragma unroll 2
    for (int c = lane; c < OC / 4; c += 32) {
        const float4 v = __ldg(hs + c);
        asm volatile("red.global.add.v4.f32 [%0], {%1, %2, %3, %4};"
                     :: "l"(zd + c), "f"(v.x * w), "f"(v.y * w), "f"(v.z * w), "f"(v.w * w)
                     : "memory");
    }
}

// ---------------------------------------------------------------------------
// mma.sync mainloop: 128x128 CTA tile, BK=64, 8 warps (2 row x 4 col),
// warp tile 64x32; split-bf16 3-MMA; 3-stage cp.async pipeline;
// register double-buffered ldmatrix fragments across k16 steps.
// ---------------------------------------------------------------------------
#define LOAD_FRAGS(s, ks) do {                                                   \
    _Pragma("unroll")                                                            \
    for (int mi = 0; mi < 4; mi++) {                                             \
        ldsm_x4(ah[s][mi], tile_addr(tAh, a_row + mi * 16, (ks) * 32 + a_kb));   \
        ldsm_x4(al[s][mi], tile_addr(tAl, a_row + mi * 16, (ks) * 32 + a_kb));   \
    }                                                                            \
    _Pragma("unroll")                                                            \
    for (int ni = 0; ni < 4; ni++) {                                             \
        ldsm_x2(bh[s][ni], tile_addr(tBh, b_row + ni * 8, (ks) * 32 + b_kb));    \
        ldsm_x2(bl[s][ni], tile_addr(tBl, b_row + ni * 8, (ks) * 32 + b_kb));    \
    }                                                                            \
} while (0)

template<int NITER, int LAST_KS>
__device__ __forceinline__ void mma_mainloop(float acc[4][4][4], uint32_t sb,
    const __nv_bfloat16* Ahi, const __nv_bfloat16* Alo, int arow0, int astride,
    const __nv_bfloat16* Bhi, const __nv_bfloat16* Blo, int brow0, int bstride)
{
    const int wid = threadIdx.x >> 5;
    const int lane = threadIdx.x & 31;
    const int wrbase = (wid >> 2) * 64;   // warp row base (0 or 64)
    const int wcbase = (wid & 3) * 32;    // warp col base (0,32,64,96)

    const int a_row = wrbase + (lane & 15);
    const int a_kb  = (lane >> 4) * 16;
    const int b_row = wcbase + (lane & 7);
    const int b_kb  = ((lane >> 3) & 1) * 16;

    // prologue: fill stages 0 and 1
    fill_stage(sb + 0 * BUF_B, 0, Ahi, Alo, arow0, astride, Bhi, Blo, brow0, bstride);
    CP_COMMIT();
    fill_stage(sb + 1 * BUF_B, 64, Ahi, Alo, arow0, astride, Bhi, Blo, brow0, bstride);
    CP_COMMIT();

    int st = 0;
    int fill_st = 2;
    #pragma unroll 1
    for (int iter = 0; iter < NITER; ++iter) {
        CP_WAIT(1);            // stage `st` complete (exactly 2 groups pending at entry)
        __syncthreads();       // all warps done reading the stage `fill_st` overwrites

        if (iter + 2 < NITER)
            fill_stage(sb + fill_st * BUF_B, (iter + 2) * 64,
                       Ahi, Alo, arow0, astride, Bhi, Blo, brow0, bstride);
        CP_COMMIT();           // always commit (possibly empty) to keep the count exact

        const uint32_t tAh = sb + st * BUF_B + 0 * TILE_B;
        const uint32_t tAl = sb + st * BUF_B + 1 * TILE_B;
        const uint32_t tBh = sb + st * BUF_B + 2 * TILE_B;
        const uint32_t tBl = sb + st * BUF_B + 3 * TILE_B;
        // For LAST_KS==4 this folds to the constant 4 (no tail branch in gemm1).
        const int nks = (iter == NITER - 1) ? LAST_KS : 4;

        uint32_t ah[2][4][4], al[2][4][4], bh[2][4][2], bl[2][4][2];
        LOAD_FRAGS(0, 0);
        #pragma unroll
        for (int ks = 0; ks < 4; ks++) {
            if (ks >= nks) break;
            const int cur = ks & 1;
            if (ks + 1 < nks) {
                const int nxt = (ks + 1) & 1;
                LOAD_FRAGS(nxt, ks + 1);
            }
            #pragma unroll
            for (int mi = 0; mi < 4; mi++)
                #pragma unroll
                for (int ni = 0; ni < 4; ni++) {
                    mma16816(acc[mi][ni], ah[cur][mi], bh[cur][ni]);
                    mma16816(acc[mi][ni], ah[cur][mi], bl[cur][ni]);
                    mma16816(acc[mi][ni], al[cur][mi], bh[cur][ni]);
                }
        }
        st = (st == NSTAGE - 1) ? 0 : st + 1;
        fill_st = (fill_st == NSTAGE - 1) ? 0 : fill_st + 1;
    }
}

// ---------------------------------------------------------------------------
// GEMM1: [g_h | g_z] (4096 x 400) = x @ [W_rel | W_root]    grid (4, 32)
// ---------------------------------------------------------------------------
__global__ __launch_bounds__(256) void gemm1_mma(const float* __restrict__ b_rel) {
    extern __shared__ __align__(1024) char smem[];
    const uint32_t sb = smem_u32(smem);
    const int rowBase = blockIdx.y * 128;
    const int colBase = blockIdx.x * 128;

    float acc[4][4][4];
    #pragma unroll
    for (int i = 0; i < 4; i++)
        #pragma unroll
        for (int j = 0; j < 4; j++)
            #pragma unroll
            for (int t = 0; t < 4; t++) acc[i][j][t] = 0.f;

    mma_mainloop<NN / 64, 4>(acc, sb, g_xhi, g_xlo, rowBase, NN, g_w1hi, g_w1lo, colBase, NN);

    const int wid = threadIdx.x >> 5, lane = threadIdx.x & 31;
    const int wrbase = (wid >> 2) * 64, wcbase = (wid & 3) * 32;
    #pragma unroll
    for (int mi = 0; mi < 4; mi++) {
        #pragma unroll
        for (int ni = 0; ni < 4; ni++) {
            const int r0 = rowBase + wrbase + mi * 16 + (lane >> 2);
            const int gc = colBase + wcbase + ni * 8 + (lane & 3) * 2;
            #pragma unroll
            for (int h = 0; h < 2; h++) {
                const int r = r0 + h * 8;
                const float v0 = acc[mi][ni][h * 2 + 0];
                const float v1 = acc[mi][ni][h * 2 + 1];
                if (gc < OC) {
                    g_h[r * OC + gc] = v0;
                    g_h[r * OC + gc + 1] = v1;
                } else if (gc < 2 * OC) {
                    const int c = gc - OC;
                    g_z[r * OC + c] = v0 + __ldg(&b_rel[c]);
                    if (c + 1 < OC) g_z[r * OC + c + 1] = v1 + __ldg(&b_rel[c + 1]);
                }
            }
        }
    }
}

// ---------------------------------------------------------------------------
// GEMM2: out (4096 x 4096) = relu(z) @ W_dec + b_dec    grid (32, 32)
// Effective K = 208 (13 k16-steps): niter=4, last iteration 1 step.
// ---------------------------------------------------------------------------
__global__ __launch_bounds__(256) void gemm2_mma(const float* __restrict__ b_dec,
                                                 float* __restrict__ out) {
    extern __shared__ __align__(1024) char smem[];
    const uint32_t sb = smem_u32(smem);
    const int rowBase = blockIdx.y * 128;
    const int colBase = blockIdx.x * 128;

    float acc[4][4][4];
    #pragma unroll
    for (int i = 0; i < 4; i++)
        #pragma unroll
        for (int j = 0; j < 4; j++)
            #pragma unroll
            for (int t = 0; t < 4; t++) acc[i][j][t] = 0.f;

    mma_mainloop<4, 1>(acc, sb, g_zhi, g_zlo, rowBase, KPAD, g_wdhi, g_wdlo, colBase, KPAD);

    const int wid = threadIdx.x >> 5, lane = threadIdx.x & 31;
    const int wrbase = (wid >> 2) * 64, wcbase = (wid & 3) * 32;
    #pragma unroll
    for (int mi = 0; mi < 4; mi++) {
        #pragma unroll
        for (int ni = 0; ni < 4; ni++) {
            const int r0 = rowBase + wrbase + mi * 16 + (lane >> 2);
            const int gc = colBase + wcbase + ni * 8 + (lane & 3) * 2;
            const float b0 = __ldg(&b_dec[gc]);
            const float b1 = __ldg(&b_dec[gc + 1]);
            #pragma unroll
            for (int h = 0; h < 2; h++) {
                const int r = r0 + h * 8;
                float2 o;
                o.x = acc[mi][ni][h * 2 + 0] + b0;
                o.y = acc[mi][ni][h * 2 + 1] + b1;
                *reinterpret_cast<float2*>(&out[(size_t)r * NN + gc]) = o;
            }
        }
    }
}

// ---------------------------------------------------------------------------
// Launch.  Inputs: x, edge_index, edge_weight, W_rel, b_rel, W_root, W_dec, b_dec
// ---------------------------------------------------------------------------
extern "C" void kernel_launch(void* const* d_in, const int* in_sizes, int n_in,
                              void* d_out, int out_size) {
    const float* x      = (const float*)d_in[0];
    const int*   ei     = (const int*)  d_in[1];
    const float* ew     = (const float*)d_in[2];
    const float* W_rel  = (const float*)d_in[3];
    const float* b_rel  = (const float*)d_in[4];
    const float* W_root = (const float*)d_in[5];
    const float* W_dec  = (const float*)d_in[6];
    const float* b_dec  = (const float*)d_in[7];
    float* out = (float*)d_out;

    cudaFuncSetAttribute(gemm1_mma, cudaFuncAttributeMaxDynamicSharedMemorySize, SMEM_TOTAL);
    cudaFuncSetAttribute(gemm2_mma, cudaFuncAttributeMaxDynamicSharedMemorySize, SMEM_TOTAL);

    conv_pre_kernel<<<28672, 256>>>(x, W_rel, W_root, W_dec);

    gemm1_mma<<<dim3(4, 32), 256, SMEM_TOTAL>>>(b_rel);
    scatter_kernel<<<8192, 256>>>(ei, ew);
    conv_z_kernel<<<512, 256>>>();
    gemm2_mma<<<dim3(32, 32), 256, SMEM_TOTAL>>>(b_dec, out);
}

// round 6
// speedup vs baseline: 1.3332x; 1.3332x over previous
#include <cuda_runtime.h>
#include <cuda_fp16.h>
#include <stdint.h>

#define NN   4096
#define EE   65536
#define OC   200
#define KPAD 256    // padded K for GEMM2
#define NCAT 512    // padded N for GEMM1 weight concat

// ---------------------------------------------------------------------------
// Scratch (device globals; no runtime allocation allowed)
// ---------------------------------------------------------------------------
__device__ __align__(16) __half g_xh[(size_t)NN * NN];    // x as fp16 (single), 32 MB
__device__ __align__(16) __half g_w1hi[NCAT * NN];        // [n,k] = Wcat[k,n], exact split
__device__ __align__(16) __half g_w1lo[NCAT * NN];
__device__ __align__(16) float g_h[NN * OC];
__device__ __align__(16) float g_z[NN * OC];
__device__ __align__(16) __half g_zh[NN * KPAD];          // relu(z) as fp16, K-padded
__device__ __align__(16) __half g_wdhi[NN * KPAD];        // [n,k] = W_dec[k,n], exact split
__device__ __align__(16) __half g_wdlo[NN * KPAD];

// ---------------------------------------------------------------------------
// PTX helpers (sm_100 baseline target: ldmatrix + mma.sync)
// ---------------------------------------------------------------------------
__device__ __forceinline__ uint32_t smem_u32(const void* p) {
    uint32_t a;
    asm("{ .reg .u64 t; cvta.to.shared.u64 t, %1; cvt.u32.u64 %0, t; }" : "=r"(a) : "l"(p));
    return a;
}
#define CP16(sa, gp)  asm volatile("cp.async.cg.shared.global [%0], [%1], 16;" :: "r"(sa), "l"(gp))
#define CP_COMMIT()   asm volatile("cp.async.commit_group;" ::: "memory")
#define CP_WAIT(n)    asm volatile("cp.async.wait_group %0;" :: "n"(n) : "memory")

__device__ __forceinline__ void ldsm_x4(uint32_t* r, uint32_t addr) {
    asm volatile("ldmatrix.sync.aligned.m8n8.x4.shared.b16 {%0,%1,%2,%3}, [%4];"
                 : "=r"(r[0]), "=r"(r[1]), "=r"(r[2]), "=r"(r[3]) : "r"(addr));
}
__device__ __forceinline__ void ldsm_x2(uint32_t* r, uint32_t addr) {
    asm volatile("ldmatrix.sync.aligned.m8n8.x2.shared.b16 {%0,%1}, [%2];"
                 : "=r"(r[0]), "=r"(r[1]) : "r"(addr));
}
__device__ __forceinline__ void mma16816(float* d, const uint32_t* a, const uint32_t* b) {
    asm volatile("mma.sync.aligned.m16n8k16.row.col.f32.f16.f16.f32 "
                 "{%0,%1,%2,%3}, {%4,%5,%6,%7}, {%8,%9}, {%0,%1,%2,%3};"
                 : "+f"(d[0]), "+f"(d[1]), "+f"(d[2]), "+f"(d[3])
                 : "r"(a[0]), "r"(a[1]), "r"(a[2]), "r"(a[3]), "r"(b[0]), "r"(b[1]));
}

// SW128-style swizzle for 128-byte rows
__device__ __forceinline__ uint32_t tile_addr(uint32_t base, int row, int kbyte) {
    uint32_t off = row * 128 + kbyte;
    return base + (off ^ ((off >> 3) & 0x70));
}

// SMEM: 3 stages x 3 tiles (A, Bhi, Blo) x 16KB (128 rows x 128B)
#define TILE_B     16384
#define BUF_B      (3 * TILE_B)          // 48 KB per stage
#define NSTAGE     3
#define SMEM_TOTAL (NSTAGE * BUF_B)      // 147456

// Fill one 128-row x 64-col fp16 tile (swizzled), 256 threads, 4x16B each.
__device__ __forceinline__ void fill_tile(uint32_t sbase, const __half* __restrict__ gsrc,
                                          int row0, int stride, int k0) {
    const int tid = threadIdx.x;
    #pragma unroll
    for (int t = 0; t < 4; t++) {
        const int q = tid + t * 256;              // 0..1023 16B chunks
        const int r = q >> 3;
        const int c16 = q & 7;
        uint32_t off = r * 128 + c16 * 16;
        uint32_t sw = off ^ ((off >> 3) & 0x70);
        const void* gp = gsrc + (size_t)(row0 + r) * stride + k0 + c16 * 8;
        CP16(sbase + sw, gp);
    }
}

__device__ __forceinline__ void fill_stage(uint32_t sbase, int k0,
    const __half* A, int arow0, int astride,
    const __half* Bhi, const __half* Blo, int brow0, int bstride)
{
    fill_tile(sbase + 0 * TILE_B, A,   arow0, astride, k0);
    fill_tile(sbase + 1 * TILE_B, Bhi, brow0, bstride, k0);
    fill_tile(sbase + 2 * TILE_B, Blo, brow0, bstride, k0);
}

// ---------------------------------------------------------------------------
// Preprocessing
// ---------------------------------------------------------------------------
__device__ __forceinline__ void splith(float v, __half& h, __half& l) {
    h = __float2half(v);
    l = __float2half(v - __half2float(h));
}

__global__ __launch_bounds__(256) void conv_pre_kernel(
    const float* __restrict__ x,
    const float* __restrict__ W_rel, const float* __restrict__ W_root,
    const float* __restrict__ W_dec)
{
    const int bid = blockIdx.x;
    if (bid < 16384) {
        const size_t i = ((size_t)bid * 256 + threadIdx.x) * 4;
        float4 v = *reinterpret_cast<const float4*>(x + i);
        __half2 p0 = __half2(__float2half(v.x), __float2half(v.y));
        __half2 p1 = __half2(__float2half(v.z), __float2half(v.w));
        *reinterpret_cast<__half2*>(g_xh + i)     = p0;
        *reinterpret_cast<__half2*>(g_xh + i + 2) = p1;
    } else if (bid < 24576) {
        const int idx = (bid - 16384) * 256 + threadIdx.x;   // n*4096 + k, n<512
        const int n = idx >> 12, k = idx & 4095;
        float v = 0.f;
        if (n < OC)          v = W_rel[k * OC + n];
        else if (n < 2 * OC) v = W_root[k * OC + (n - OC)];
        __half h, l; splith(v, h, l);
        g_w1hi[idx] = h; g_w1lo[idx] = l;
    } else {
        const int idx = (bid - 24576) * 256 + threadIdx.x;   // n*256 + k
        const int n = idx >> 8, k = idx & 255;
        float v = (k < OC) ? W_dec[(size_t)k * NN + n] : 0.f;
        __half h, l; splith(v, h, l);
        g_wdhi[idx] = h; g_wdlo[idx] = l;
    }
}

// relu(z) -> fp16, 8 elems/thread; only cols < 208 consumed by gemm2.
__global__ __launch_bounds__(256) void conv_z_kernel() {
    const int idx = blockIdx.x * 256 + threadIdx.x;
    const int m = idx >> 5;
    const int kk = (idx & 31) * 8;
    if (kk >= 208) return;
    __half2 h[4];
    if (kk < OC) {
        const float4 v0 = *reinterpret_cast<const float4*>(&g_z[m * OC + kk]);
        const float4 v1 = *reinterpret_cast<const float4*>(&g_z[m * OC + kk + 4]);
        h[0] = __half2(__float2half(fmaxf(v0.x, 0.f)), __float2half(fmaxf(v0.y, 0.f)));
        h[1] = __half2(__float2half(fmaxf(v0.z, 0.f)), __float2half(fmaxf(v0.w, 0.f)));
        h[2] = __half2(__float2half(fmaxf(v1.x, 0.f)), __float2half(fmaxf(v1.y, 0.f)));
        h[3] = __half2(__float2half(fmaxf(v1.z, 0.f)), __float2half(fmaxf(v1.w, 0.f)));
    } else {
        #pragma unroll
        for (int t = 0; t < 4; t++) h[t] = __half2(__float2half(0.f), __float2half(0.f));
    }
    #pragma unroll
    for (int t = 0; t < 4; t++)
        *reinterpret_cast<__half2*>(g_zh + m * KPAD + kk + 2 * t) = h[t];
}

// ---------------------------------------------------------------------------
// Edge scatter: g_z[dst] += g_h[src] * w
// ---------------------------------------------------------------------------
__global__ __launch_bounds__(256) void scatter_kernel(const int* __restrict__ ei,
                                                      const float* __restrict__ ew) {
    const int warp = (blockIdx.x * 256 + threadIdx.x) >> 5;
    const int lane = threadIdx.x & 31;
    if (warp >= EE) return;
    const int src = ei[warp];
    const int dst = ei[EE + warp];
    const float w = ew[warp];
    const float4* hs = reinterpret_cast<const float4*>(&g_h[src * OC]);
    float4* zd = reinterpret_cast<float4*>(&g_z[dst * OC]);
    #pragma unroll 2
    for (int c = lane; c < OC / 4; c += 32) {
        const float4 v = __ldg(hs + c);
        asm volatile("red.global.add.v4.f32 [%0], {%1, %2, %3, %4};"
                     :: "l"(zd + c), "f"(v.x * w), "f"(v.y * w), "f"(v.z * w), "f"(v.w * w)
                     : "memory");
    }
}

// ---------------------------------------------------------------------------
// mma.sync mainloop: 128x128 CTA tile, BK=64, 8 warps (2 row x 4 col),
// warp tile 64x32; fp16 2-MMA (A single, B split exactly); 3-stage cp.async.
// ---------------------------------------------------------------------------
template<int NITER, int LAST_KS>
__device__ __forceinline__ void mma_mainloop(float acc[4][4][4], uint32_t sb,
    const __half* A, int arow0, int astride,
    const __half* Bhi, const __half* Blo, int brow0, int bstride)
{
    const int wid = threadIdx.x >> 5;
    const int lane = threadIdx.x & 31;
    const int wrbase = (wid >> 2) * 64;   // warp row base (0 or 64)
    const int wcbase = (wid & 3) * 32;    // warp col base (0,32,64,96)

    const int a_row = wrbase + (lane & 15);
    const int a_kb  = (lane >> 4) * 16;
    const int b_row = wcbase + (lane & 7);
    const int b_kb  = ((lane >> 3) & 1) * 16;

    // prologue: fill stages 0 and 1
    fill_stage(sb + 0 * BUF_B, 0,  A, arow0, astride, Bhi, Blo, brow0, bstride);
    CP_COMMIT();
    fill_stage(sb + 1 * BUF_B, 64, A, arow0, astride, Bhi, Blo, brow0, bstride);
    CP_COMMIT();

    int st = 0;
    int fill_st = 2;
    #pragma unroll 1
    for (int iter = 0; iter < NITER; ++iter) {
        CP_WAIT(1);            // stage `st` complete (exactly 2 groups pending at entry)
        __syncthreads();       // all warps done reading the stage `fill_st` overwrites

        if (iter + 2 < NITER)
            fill_stage(sb + fill_st * BUF_B, (iter + 2) * 64,
                       A, arow0, astride, Bhi, Blo, brow0, bstride);
        CP_COMMIT();           // always commit (possibly empty) to keep the count exact

        const uint32_t tA  = sb + st * BUF_B + 0 * TILE_B;
        const uint32_t tBh = sb + st * BUF_B + 1 * TILE_B;
        const uint32_t tBl = sb + st * BUF_B + 2 * TILE_B;
        const int nks = (iter == NITER - 1) ? LAST_KS : 4;

        #pragma unroll
        for (int ks = 0; ks < 4; ks++) {
            if (ks >= nks) break;
            uint32_t a[4][4], bh[4][2], bl[4][2];
            #pragma unroll
            for (int mi = 0; mi < 4; mi++)
                ldsm_x4(a[mi], tile_addr(tA, a_row + mi * 16, ks * 32 + a_kb));
            #pragma unroll
            for (int ni = 0; ni < 4; ni++) {
                ldsm_x2(bh[ni], tile_addr(tBh, b_row + ni * 8, ks * 32 + b_kb));
                ldsm_x2(bl[ni], tile_addr(tBl, b_row + ni * 8, ks * 32 + b_kb));
            }
            #pragma unroll
            for (int mi = 0; mi < 4; mi++)
                #pragma unroll
                for (int ni = 0; ni < 4; ni++) {
                    mma16816(acc[mi][ni], a[mi], bh[ni]);
                    mma16816(acc[mi][ni], a[mi], bl[ni]);
                }
        }
        st = (st == NSTAGE - 1) ? 0 : st + 1;
        fill_st = (fill_st == NSTAGE - 1) ? 0 : fill_st + 1;
    }
}

// ---------------------------------------------------------------------------
// GEMM1: [g_h | g_z] (4096 x 400) = x @ [W_rel | W_root]    grid (4, 32)
// ---------------------------------------------------------------------------
__global__ __launch_bounds__(256) void gemm1_mma(const float* __restrict__ b_rel) {
    extern __shared__ __align__(1024) char smem[];
    const uint32_t sb = smem_u32(smem);
    const int rowBase = blockIdx.y * 128;
    const int colBase = blockIdx.x * 128;

    float acc[4][4][4];
    #pragma unroll
    for (int i = 0; i < 4; i++)
        #pragma unroll
        for (int j = 0; j < 4; j++)
            #pragma unroll
            for (int t = 0; t < 4; t++) acc[i][j][t] = 0.f;

    mma_mainloop<NN / 64, 4>(acc, sb, g_xh, rowBase, NN, g_w1hi, g_w1lo, colBase, NN);

    const int wid = threadIdx.x >> 5, lane = threadIdx.x & 31;
    const int wrbase = (wid >> 2) * 64, wcbase = (wid & 3) * 32;
    #pragma unroll
    for (int mi = 0; mi < 4; mi++) {
        #pragma unroll
        for (int ni = 0; ni < 4; ni++) {
            const int r0 = rowBase + wrbase + mi * 16 + (lane >> 2);
            const int gc = colBase + wcbase + ni * 8 + (lane & 3) * 2;
            #pragma unroll
            for (int h = 0; h < 2; h++) {
                const int r = r0 + h * 8;
                const float v0 = acc[mi][ni][h * 2 + 0];
                const float v1 = acc[mi][ni][h * 2 + 1];
                if (gc < OC) {
                    g_h[r * OC + gc] = v0;
                    g_h[r * OC + gc + 1] = v1;
                } else if (gc < 2 * OC) {
                    const int c = gc - OC;
                    g_z[r * OC + c] = v0 + __ldg(&b_rel[c]);
                    if (c + 1 < OC) g_z[r * OC + c + 1] = v1 + __ldg(&b_rel[c + 1]);
                }
            }
        }
    }
}

// ---------------------------------------------------------------------------
// GEMM2: out (4096 x 4096) = relu(z) @ W_dec + b_dec    grid (32, 32)
// Effective K = 208 (13 k16-steps): niter=4, last iteration 1 step.
// ---------------------------------------------------------------------------
__global__ __launch_bounds__(256) void gemm2_mma(const float* __restrict__ b_dec,
                                                 float* __restrict__ out) {
    extern __shared__ __align__(1024) char smem[];
    const uint32_t sb = smem_u32(smem);
    const int rowBase = blockIdx.y * 128;
    const int colBase = blockIdx.x * 128;

    float acc[4][4][4];
    #pragma unroll
    for (int i = 0; i < 4; i++)
        #pragma unroll
        for (int j = 0; j < 4; j++)
            #pragma unroll
            for (int t = 0; t < 4; t++) acc[i][j][t] = 0.f;

    mma_mainloop<4, 1>(acc, sb, g_zh, rowBase, KPAD, g_wdhi, g_wdlo, colBase, KPAD);

    const int wid = threadIdx.x >> 5, lane = threadIdx.x & 31;
    const int wrbase = (wid >> 2) * 64, wcbase = (wid & 3) * 32;
    #pragma unroll
    for (int mi = 0; mi < 4; mi++) {
        #pragma unroll
        for (int ni = 0; ni < 4; ni++) {
            const int r0 = rowBase + wrbase + mi * 16 + (lane >> 2);
            const int gc = colBase + wcbase + ni * 8 + (lane & 3) * 2;
            const float b0 = __ldg(&b_dec[gc]);
            const float b1 = __ldg(&b_dec[gc + 1]);
            #pragma unroll
            for (int h = 0; h < 2; h++) {
                const int r = r0 + h * 8;
                float2 o;
                o.x = acc[mi][ni][h * 2 + 0] + b0;
                o.y = acc[mi][ni][h * 2 + 1] + b1;
                *reinterpret_cast<float2*>(&out[(size_t)r * NN + gc]) = o;
            }
        }
    }
}

// ---------------------------------------------------------------------------
// Launch.  Inputs: x, edge_index, edge_weight, W_rel, b_rel, W_root, W_dec, b_dec
// ---------------------------------------------------------------------------
extern "C" void kernel_launch(void* const* d_in, const int* in_sizes, int n_in,
                              void* d_out, int out_size) {
    const float* x      = (const float*)d_in[0];
    const int*   ei     = (const int*)  d_in[1];
    const float* ew     = (const float*)d_in[2];
    const float* W_rel  = (const float*)d_in[3];
    const float* b_rel  = (const float*)d_in[4];
    const float* W_root = (const float*)d_in[5];
    const float* W_dec  = (const float*)d_in[6];
    const float* b_dec  = (const float*)d_in[7];
    float* out = (float*)d_out;

    cudaFuncSetAttribute(gemm1_mma, cudaFuncAttributeMaxDynamicSharedMemorySize, SMEM_TOTAL);
    cudaFuncSetAttribute(gemm2_mma, cudaFuncAttributeMaxDynamicSharedMemorySize, SMEM_TOTAL);

    conv_pre_kernel<<<28672, 256>>>(x, W_rel, W_root, W_dec);

    gemm1_mma<<<dim3(4, 32), 256, SMEM_TOTAL>>>(b_rel);
    scatter_kernel<<<8192, 256>>>(ei, ew);
    conv_z_kernel<<<512, 256>>>();
    gemm2_mma<<<dim3(32, 32), 256, SMEM_TOTAL>>>(b_dec, out);
}

// round 7
// speedup vs baseline: 1.3334x; 1.0002x over previous
#include <cuda_runtime.h>
#include <cuda_fp16.h>
#include <stdint.h>

#define NN   4096
#define EE   65536
#define OC   200
#define KPAD 256    // padded K for GEMM2
#define NCAT 512    // padded N for GEMM1 weight concat

// ---------------------------------------------------------------------------
// Scratch (device globals; no runtime allocation allowed)
// ---------------------------------------------------------------------------
__device__ __align__(16) __half g_xh[(size_t)NN * NN];    // x as fp16 (single), 32 MB
__device__ __align__(16) __half g_w1hi[NCAT * NN];        // [n,k] = Wcat[k,n], exact split
__device__ __align__(16) __half g_w1lo[NCAT * NN];
__device__ __align__(16) float g_h[NN * OC];
__device__ __align__(16) float g_z[NN * OC];
__device__ __align__(16) __half g_zh[NN * KPAD];          // relu(z) as fp16, K-padded
__device__ __align__(16) __half g_wdhi[NN * KPAD];        // [n,k] = W_dec[k,n], exact split
__device__ __align__(16) __half g_wdlo[NN * KPAD];

// ---------------------------------------------------------------------------
// PTX helpers
// ---------------------------------------------------------------------------
__device__ __forceinline__ uint32_t smem_u32(const void* p) {
    uint32_t a;
    asm("{ .reg .u64 t; cvta.to.shared.u64 t, %1; cvt.u32.u64 %0, t; }" : "=r"(a) : "l"(p));
    return a;
}
#define CP16(sa, gp)  asm volatile("cp.async.cg.shared.global [%0], [%1], 16;" :: "r"(sa), "l"(gp))
#define CP_COMMIT()   asm volatile("cp.async.commit_group;" ::: "memory")
#define CP_WAIT(n)    asm volatile("cp.async.wait_group %0;" :: "n"(n) : "memory")

__device__ __forceinline__ void ldsm_x4(uint32_t* r, uint32_t addr) {
    asm volatile("ldmatrix.sync.aligned.m8n8.x4.shared.b16 {%0,%1,%2,%3}, [%4];"
                 : "=r"(r[0]), "=r"(r[1]), "=r"(r[2]), "=r"(r[3]) : "r"(addr));
}
__device__ __forceinline__ void ldsm_x2(uint32_t* r, uint32_t addr) {
    asm volatile("ldmatrix.sync.aligned.m8n8.x2.shared.b16 {%0,%1}, [%2];"
                 : "=r"(r[0]), "=r"(r[1]) : "r"(addr));
}
__device__ __forceinline__ void mma16816(float* d, const uint32_t* a, const uint32_t* b) {
    asm volatile("mma.sync.aligned.m16n8k16.row.col.f32.f16.f16.f32 "
                 "{%0,%1,%2,%3}, {%4,%5,%6,%7}, {%8,%9}, {%0,%1,%2,%3};"
                 : "+f"(d[0]), "+f"(d[1]), "+f"(d[2]), "+f"(d[3])
                 : "r"(a[0]), "r"(a[1]), "r"(a[2]), "r"(a[3]), "r"(b[0]), "r"(b[1]));
}

// SW128-style swizzle for 128-byte rows
__device__ __forceinline__ uint32_t tile_addr(uint32_t base, int row, int kbyte) {
    uint32_t off = row * 128 + kbyte;
    return base + (off ^ ((off >> 3) & 0x70));
}

// SMEM: 2 stages x (A 64x64 fp16 = 8KB, Bhi 128x64 = 16KB, Blo = 16KB) = 40KB/stage
#define A_TILE_B   8192
#define B_TILE_B   16384
#define OFF_A      0
#define OFF_BH     8192
#define OFF_BL     24576
#define BUF_B      40960
#define NSTAGE     2
#define SMEM_TOTAL (NSTAGE * BUF_B)      // 81920

// Fill one ROWS x 64-col fp16 tile (swizzled), 256 threads.
template<int ROWS>
__device__ __forceinline__ void fill_tile(uint32_t sbase, const __half* __restrict__ gsrc,
                                          int row0, int stride, int k0) {
    const int tid = threadIdx.x;
    #pragma unroll
    for (int t = 0; t < ROWS / 32; t++) {            // ROWS*8 chunks / 256 threads
        const int q = tid + t * 256;
        const int r = q >> 3;
        const int c16 = q & 7;
        uint32_t off = r * 128 + c16 * 16;
        uint32_t sw = off ^ ((off >> 3) & 0x70);
        const void* gp = gsrc + (size_t)(row0 + r) * stride + k0 + c16 * 8;
        CP16(sbase + sw, gp);
    }
}

__device__ __forceinline__ void fill_stage(uint32_t sbase, int k0,
    const __half* A, int arow0, int astride,
    const __half* Bhi, const __half* Blo, int brow0, int bstride)
{
    fill_tile<64>(sbase + OFF_A,  A,   arow0, astride, k0);
    fill_tile<128>(sbase + OFF_BH, Bhi, brow0, bstride, k0);
    fill_tile<128>(sbase + OFF_BL, Blo, brow0, bstride, k0);
}

// ---------------------------------------------------------------------------
// Preprocessing
// ---------------------------------------------------------------------------
__device__ __forceinline__ void splith(float v, __half& h, __half& l) {
    h = __float2half(v);
    l = __float2half(v - __half2float(h));
}

__global__ __launch_bounds__(256) void conv_pre_kernel(
    const float* __restrict__ x,
    const float* __restrict__ W_rel, const float* __restrict__ W_root,
    const float* __restrict__ W_dec)
{
    const int bid = blockIdx.x;
    if (bid < 16384) {
        const size_t i = ((size_t)bid * 256 + threadIdx.x) * 4;
        float4 v = *reinterpret_cast<const float4*>(x + i);
        __half2 p0 = __half2(__float2half(v.x), __float2half(v.y));
        __half2 p1 = __half2(__float2half(v.z), __float2half(v.w));
        *reinterpret_cast<__half2*>(g_xh + i)     = p0;
        *reinterpret_cast<__half2*>(g_xh + i + 2) = p1;
    } else if (bid < 24576) {
        const int idx = (bid - 16384) * 256 + threadIdx.x;   // n*4096 + k, n<512
        const int n = idx >> 12, k = idx & 4095;
        float v = 0.f;
        if (n < OC)          v = W_rel[k * OC + n];
        else if (n < 2 * OC) v = W_root[k * OC + (n - OC)];
        __half h, l; splith(v, h, l);
        g_w1hi[idx] = h; g_w1lo[idx] = l;
    } else {
        const int idx = (bid - 24576) * 256 + threadIdx.x;   // n*256 + k
        const int n = idx >> 8, k = idx & 255;
        float v = (k < OC) ? W_dec[(size_t)k * NN + n] : 0.f;
        __half h, l; splith(v, h, l);
        g_wdhi[idx] = h; g_wdlo[idx] = l;
    }
}

// relu(z) -> fp16, 8 elems/thread; only cols < 208 consumed by gemm2.
__global__ __launch_bounds__(256) void conv_z_kernel() {
    const int idx = blockIdx.x * 256 + threadIdx.x;
    const int m = idx >> 5;
    const int kk = (idx & 31) * 8;
    if (kk >= 208) return;
    __half2 h[4];
    if (kk < OC) {
        const float4 v0 = *reinterpret_cast<const float4*>(&g_z[m * OC + kk]);
        const float4 v1 = *reinterpret_cast<const float4*>(&g_z[m * OC + kk + 4]);
        h[0] = __half2(__float2half(fmaxf(v0.x, 0.f)), __float2half(fmaxf(v0.y, 0.f)));
        h[1] = __half2(__float2half(fmaxf(v0.z, 0.f)), __float2half(fmaxf(v0.w, 0.f)));
        h[2] = __half2(__float2half(fmaxf(v1.x, 0.f)), __float2half(fmaxf(v1.y, 0.f)));
        h[3] = __half2(__float2half(fmaxf(v1.z, 0.f)), __float2half(fmaxf(v1.w, 0.f)));
    } else {
        #pragma unroll
        for (int t = 0; t < 4; t++) h[t] = __half2(__float2half(0.f), __float2half(0.f));
    }
    #pragma unroll
    for (int t = 0; t < 4; t++)
        *reinterpret_cast<__half2*>(g_zh + m * KPAD + kk + 2 * t) = h[t];
}

// ---------------------------------------------------------------------------
// Edge scatter: g_z[dst] += g_h[src] * w
// ---------------------------------------------------------------------------
__global__ __launch_bounds__(256) void scatter_kernel(const int* __restrict__ ei,
                                                      const float* __restrict__ ew) {
    const int warp = (blockIdx.x * 256 + threadIdx.x) >> 5;
    const int lane = threadIdx.x & 31;
    if (warp >= EE) return;
    const int src = ei[warp];
    const int dst = ei[EE + warp];
    const float w = ew[warp];
    const float4* hs = reinterpret_cast<const float4*>(&g_h[src * OC]);
    float4* zd = reinterpret_cast<float4*>(&g_z[dst * OC]);
    #pragma unroll 2
    for (int c = lane; c < OC / 4; c += 32) {
        const float4 v = __ldg(hs + c);
        asm volatile("red.global.add.v4.f32 [%0], {%1, %2, %3, %4};"
                     :: "l"(zd + c), "f"(v.x * w), "f"(v.y * w), "f"(v.z * w), "f"(v.w * w)
                     : "memory");
    }
}

// ---------------------------------------------------------------------------
// mma.sync mainloop: 64x128 CTA tile, BK=64, 8 warps (2 row x 4 col),
// warp tile 32x32 (mi=2); fp16 2-MMA; 2-stage cp.async double buffer.
// ---------------------------------------------------------------------------
template<int NITER, int LAST_KS>
__device__ __forceinline__ void mma_mainloop(float acc[2][4][4], uint32_t sb,
    const __half* A, int arow0, int astride,
    const __half* Bhi, const __half* Blo, int brow0, int bstride)
{
    const int wid = threadIdx.x >> 5;
    const int lane = threadIdx.x & 31;
    const int wrbase = (wid >> 2) * 32;   // warp row base (0 or 32)
    const int wcbase = (wid & 3) * 32;    // warp col base (0,32,64,96)

    const int a_row = wrbase + (lane & 15);
    const int a_kb  = (lane >> 4) * 16;
    const int b_row = wcbase + (lane & 7);
    const int b_kb  = ((lane >> 3) & 1) * 16;

    // prologue: fill stage 0
    fill_stage(sb + 0 * BUF_B, 0, A, arow0, astride, Bhi, Blo, brow0, bstride);
    CP_COMMIT();

    #pragma unroll 1
    for (int iter = 0; iter < NITER; ++iter) {
        const int st = iter & 1;
        CP_WAIT(0);            // all outstanding fills done (stage `st` ready)
        __syncthreads();       // stage data visible; stage st^1 fully consumed

        if (iter + 1 < NITER) {
            fill_stage(sb + (st ^ 1) * BUF_B, (iter + 1) * 64,
                       A, arow0, astride, Bhi, Blo, brow0, bstride);
            CP_COMMIT();
        }

        const uint32_t tA  = sb + st * BUF_B + OFF_A;
        const uint32_t tBh = sb + st * BUF_B + OFF_BH;
        const uint32_t tBl = sb + st * BUF_B + OFF_BL;
        const int nks = (iter == NITER - 1) ? LAST_KS : 4;

        #pragma unroll
        for (int ks = 0; ks < 4; ks++) {
            if (ks >= nks) break;
            uint32_t a[2][4], bh[4][2], bl[4][2];
            #pragma unroll
            for (int mi = 0; mi < 2; mi++)
                ldsm_x4(a[mi], tile_addr(tA, a_row + mi * 16, ks * 32 + a_kb));
            #pragma unroll
            for (int ni = 0; ni < 4; ni++) {
                ldsm_x2(bh[ni], tile_addr(tBh, b_row + ni * 8, ks * 32 + b_kb));
                ldsm_x2(bl[ni], tile_addr(tBl, b_row + ni * 8, ks * 32 + b_kb));
            }
            #pragma unroll
            for (int mi = 0; mi < 2; mi++)
                #pragma unroll
                for (int ni = 0; ni < 4; ni++) {
                    mma16816(acc[mi][ni], a[mi], bh[ni]);
                    mma16816(acc[mi][ni], a[mi], bl[ni]);
                }
        }
    }
}

// ---------------------------------------------------------------------------
// GEMM1: [g_h | g_z] (4096 x 400) = x @ [W_rel | W_root]    grid (4, 64)
// ---------------------------------------------------------------------------
__global__ __launch_bounds__(256, 2) void gemm1_mma(const float* __restrict__ b_rel) {
    extern __shared__ __align__(1024) char smem[];
    const uint32_t sb = smem_u32(smem);
    const int rowBase = blockIdx.y * 64;
    const int colBase = blockIdx.x * 128;

    float acc[2][4][4];
    #pragma unroll
    for (int i = 0; i < 2; i++)
        #pragma unroll
        for (int j = 0; j < 4; j++)
            #pragma unroll
            for (int t = 0; t < 4; t++) acc[i][j][t] = 0.f;

    mma_mainloop<NN / 64, 4>(acc, sb, g_xh, rowBase, NN, g_w1hi, g_w1lo, colBase, NN);

    const int wid = threadIdx.x >> 5, lane = threadIdx.x & 31;
    const int wrbase = (wid >> 2) * 32, wcbase = (wid & 3) * 32;
    #pragma unroll
    for (int mi = 0; mi < 2; mi++) {
        #pragma unroll
        for (int ni = 0; ni < 4; ni++) {
            const int r0 = rowBase + wrbase + mi * 16 + (lane >> 2);
            const int gc = colBase + wcbase + ni * 8 + (lane & 3) * 2;
            #pragma unroll
            for (int h = 0; h < 2; h++) {
                const int r = r0 + h * 8;
                const float v0 = acc[mi][ni][h * 2 + 0];
                const float v1 = acc[mi][ni][h * 2 + 1];
                if (gc < OC) {
                    g_h[r * OC + gc] = v0;
                    g_h[r * OC + gc + 1] = v1;
                } else if (gc < 2 * OC) {
                    const int c = gc - OC;
                    g_z[r * OC + c] = v0 + __ldg(&b_rel[c]);
                    if (c + 1 < OC) g_z[r * OC + c + 1] = v1 + __ldg(&b_rel[c + 1]);
                }
            }
        }
    }
}

// ---------------------------------------------------------------------------
// GEMM2: out (4096 x 4096) = relu(z) @ W_dec + b_dec    grid (32, 64)
// Effective K = 208 (13 k16-steps): niter=4, last iteration 1 step.
// ---------------------------------------------------------------------------
__global__ __launch_bounds__(256, 2) void gemm2_mma(const float* __restrict__ b_dec,
                                                    float* __restrict__ out) {
    extern __shared__ __align__(1024) char smem[];
    const uint32_t sb = smem_u32(smem);
    const int rowBase = blockIdx.y * 64;
    const int colBase = blockIdx.x * 128;

    float acc[2][4][4];
    #pragma unroll
    for (int i = 0; i < 2; i++)
        #pragma unroll
        for (int j = 0; j < 4; j++)
            #pragma unroll
            for (int t = 0; t < 4; t++) acc[i][j][t] = 0.f;

    mma_mainloop<4, 1>(acc, sb, g_zh, rowBase, KPAD, g_wdhi, g_wdlo, colBase, KPAD);

    const int wid = threadIdx.x >> 5, lane = threadIdx.x & 31;
    const int wrbase = (wid >> 2) * 32, wcbase = (wid & 3) * 32;
    #pragma unroll
    for (int mi = 0; mi < 2; mi++) {
        #pragma unroll
        for (int ni = 0; ni < 4; ni++) {
            const int r0 = rowBase + wrbase + mi * 16 + (lane >> 2);
            const int gc = colBase + wcbase + ni * 8 + (lane & 3) * 2;
            const float b0 = __ldg(&b_dec[gc]);
            const float b1 = __ldg(&b_dec[gc + 1]);
            #pragma unroll
            for (int h = 0; h < 2; h++) {
                const int r = r0 + h * 8;
                float2 o;
                o.x = acc[mi][ni][h * 2 + 0] + b0;
                o.y = acc[mi][ni][h * 2 + 1] + b1;
                *reinterpret_cast<float2*>(&out[(size_t)r * NN + gc]) = o;
            }
        }
    }
}

// ---------------------------------------------------------------------------
// Launch.  Inputs: x, edge_index, edge_weight, W_rel, b_rel, W_root, W_dec, b_dec
// ---------------------------------------------------------------------------
extern "C" void kernel_launch(void* const* d_in, const int* in_sizes, int n_in,
                              void* d_out, int out_size) {
    const float* x      = (const float*)d_in[0];
    const int*   ei     = (const int*)  d_in[1];
    const float* ew     = (const float*)d_in[2];
    const float* W_rel  = (const float*)d_in[3];
    const float* b_rel  = (const float*)d_in[4];
    const float* W_root = (const float*)d_in[5];
    const float* W_dec  = (const float*)d_in[6];
    const float* b_dec  = (const float*)d_in[7];
    float* out = (float*)d_out;

    cudaFuncSetAttribute(gemm1_mma, cudaFuncAttributeMaxDynamicSharedMemorySize, SMEM_TOTAL);
    cudaFuncSetAttribute(gemm2_mma, cudaFuncAttributeMaxDynamicSharedMemorySize, SMEM_TOTAL);

    conv_pre_kernel<<<28672, 256>>>(x, W_rel, W_root, W_dec);

    gemm1_mma<<<dim3(4, 64), 256, SMEM_TOTAL>>>(b_rel);
    scatter_kernel<<<8192, 256>>>(ei, ew);
    conv_z_kernel<<<512, 256>>>();
    gemm2_mma<<<dim3(32, 64), 256, SMEM_TOTAL>>>(b_dec, out);
}

// round 8
// speedup vs baseline: 1.8315x; 1.3736x over previous
#include <cuda_runtime.h>
#include <cuda_fp16.h>
#include <stdint.h>

#define NN   4096
#define EE   65536
#define OC   200
#define KPAD 256    // padded K for GEMM2
#define NCAT 512    // padded N for GEMM1 weight concat

// ---------------------------------------------------------------------------
// Scratch (device globals; no runtime allocation allowed)
// ---------------------------------------------------------------------------
__device__ __align__(16) __half g_xh[(size_t)NN * NN];    // x as fp16, 32 MB
__device__ __align__(16) __half g_w1[NCAT * NN];          // [n,k] = Wcat[k,n]
__device__ __align__(16) float g_h[NN * OC];
__device__ __align__(16) float g_z[NN * OC];
__device__ __align__(16) __half g_zh[NN * KPAD];          // relu(z) as fp16, K-padded
__device__ __align__(16) __half g_wd[NN * KPAD];          // [n,k] = W_dec[k,n], padded

// ---------------------------------------------------------------------------
// PTX helpers
// ---------------------------------------------------------------------------
__device__ __forceinline__ uint32_t smem_u32(const void* p) {
    uint32_t a;
    asm("{ .reg .u64 t; cvta.to.shared.u64 t, %1; cvt.u32.u64 %0, t; }" : "=r"(a) : "l"(p));
    return a;
}
#define CP16(sa, gp)  asm volatile("cp.async.cg.shared.global [%0], [%1], 16;" :: "r"(sa), "l"(gp))
#define CP_COMMIT()   asm volatile("cp.async.commit_group;" ::: "memory")
#define CP_WAIT(n)    asm volatile("cp.async.wait_group %0;" :: "n"(n) : "memory")

__device__ __forceinline__ void ldsm_x4(uint32_t* r, uint32_t addr) {
    asm volatile("ldmatrix.sync.aligned.m8n8.x4.shared.b16 {%0,%1,%2,%3}, [%4];"
                 : "=r"(r[0]), "=r"(r[1]), "=r"(r[2]), "=r"(r[3]) : "r"(addr));
}
__device__ __forceinline__ void ldsm_x2(uint32_t* r, uint32_t addr) {
    asm volatile("ldmatrix.sync.aligned.m8n8.x2.shared.b16 {%0,%1}, [%2];"
                 : "=r"(r[0]), "=r"(r[1]) : "r"(addr));
}
__device__ __forceinline__ void mma16816(float* d, const uint32_t* a, const uint32_t* b) {
    asm volatile("mma.sync.aligned.m16n8k16.row.col.f32.f16.f16.f32 "
                 "{%0,%1,%2,%3}, {%4,%5,%6,%7}, {%8,%9}, {%0,%1,%2,%3};"
                 : "+f"(d[0]), "+f"(d[1]), "+f"(d[2]), "+f"(d[3])
                 : "r"(a[0]), "r"(a[1]), "r"(a[2]), "r"(a[3]), "r"(b[0]), "r"(b[1]));
}

// SW128-style swizzle for 128-byte rows
__device__ __forceinline__ uint32_t tile_addr(uint32_t base, int row, int kbyte) {
    uint32_t off = row * 128 + kbyte;
    return base + (off ^ ((off >> 3) & 0x70));
}

// SMEM: 3 stages x (A 64x64 fp16 = 8KB, B 128x64 = 16KB) = 24KB/stage
#define OFF_A      0
#define OFF_B      8192
#define BUF_B      24576
#define NSTAGE     3
#define SMEM_TOTAL (NSTAGE * BUF_B)      // 73728; 2 CTAs/SM -> 147KB

// Fill one ROWS x 64-col fp16 tile (swizzled), 256 threads.
template<int ROWS>
__device__ __forceinline__ void fill_tile(uint32_t sbase, const __half* __restrict__ gsrc,
                                          int row0, int stride, int k0) {
    const int tid = threadIdx.x;
    #pragma unroll
    for (int t = 0; t < ROWS / 32; t++) {            // ROWS*8 chunks / 256 threads
        const int q = tid + t * 256;
        const int r = q >> 3;
        const int c16 = q & 7;
        uint32_t off = r * 128 + c16 * 16;
        uint32_t sw = off ^ ((off >> 3) & 0x70);
        const void* gp = gsrc + (size_t)(row0 + r) * stride + k0 + c16 * 8;
        CP16(sbase + sw, gp);
    }
}

__device__ __forceinline__ void fill_stage(uint32_t sbase, int k0,
    const __half* A, int arow0, int astride,
    const __half* B, int brow0, int bstride)
{
    fill_tile<64>(sbase + OFF_A, A, arow0, astride, k0);
    fill_tile<128>(sbase + OFF_B, B, brow0, bstride, k0);
}

// ---------------------------------------------------------------------------
// Preprocessing: fp32 -> fp16 (single rounding)
// ---------------------------------------------------------------------------
__global__ __launch_bounds__(256) void conv_pre_kernel(
    const float* __restrict__ x,
    const float* __restrict__ W_rel, const float* __restrict__ W_root,
    const float* __restrict__ W_dec)
{
    const int bid = blockIdx.x;
    if (bid < 16384) {
        const size_t i = ((size_t)bid * 256 + threadIdx.x) * 4;
        float4 v = *reinterpret_cast<const float4*>(x + i);
        *reinterpret_cast<__half2*>(g_xh + i)     = __half2(__float2half(v.x), __float2half(v.y));
        *reinterpret_cast<__half2*>(g_xh + i + 2) = __half2(__float2half(v.z), __float2half(v.w));
    } else if (bid < 24576) {
        const int idx = (bid - 16384) * 256 + threadIdx.x;   // n*4096 + k, n<512
        const int n = idx >> 12, k = idx & 4095;
        float v = 0.f;
        if (n < OC)          v = W_rel[k * OC + n];
        else if (n < 2 * OC) v = W_root[k * OC + (n - OC)];
        g_w1[idx] = __float2half(v);
    } else {
        const int idx = (bid - 24576) * 256 + threadIdx.x;   // n*256 + k
        const int n = idx >> 8, k = idx & 255;
        float v = (k < OC) ? W_dec[(size_t)k * NN + n] : 0.f;
        g_wd[idx] = __float2half(v);
    }
}

// relu(z) -> fp16, 8 elems/thread; only cols < 208 consumed by gemm2.
__global__ __launch_bounds__(256) void conv_z_kernel() {
    const int idx = blockIdx.x * 256 + threadIdx.x;
    const int m = idx >> 5;
    const int kk = (idx & 31) * 8;
    if (kk >= 208) return;
    __half2 h[4];
    if (kk < OC) {
        const float4 v0 = *reinterpret_cast<const float4*>(&g_z[m * OC + kk]);
        const float4 v1 = *reinterpret_cast<const float4*>(&g_z[m * OC + kk + 4]);
        h[0] = __half2(__float2half(fmaxf(v0.x, 0.f)), __float2half(fmaxf(v0.y, 0.f)));
        h[1] = __half2(__float2half(fmaxf(v0.z, 0.f)), __float2half(fmaxf(v0.w, 0.f)));
        h[2] = __half2(__float2half(fmaxf(v1.x, 0.f)), __float2half(fmaxf(v1.y, 0.f)));
        h[3] = __half2(__float2half(fmaxf(v1.z, 0.f)), __float2half(fmaxf(v1.w, 0.f)));
    } else {
        #pragma unroll
        for (int t = 0; t < 4; t++) h[t] = __half2(__float2half(0.f), __float2half(0.f));
    }
    #pragma unroll
    for (int t = 0; t < 4; t++)
        *reinterpret_cast<__half2*>(g_zh + m * KPAD + kk + 2 * t) = h[t];
}

// ---------------------------------------------------------------------------
// Edge scatter: g_z[dst] += g_h[src] * w
// ---------------------------------------------------------------------------
__global__ __launch_bounds__(256) void scatter_kernel(const int* __restrict__ ei,
                                                      const float* __restrict__ ew) {
    const int warp = (blockIdx.x * 256 + threadIdx.x) >> 5;
    const int lane = threadIdx.x & 31;
    if (warp >= EE) return;
    const int src = ei[warp];
    const int dst = ei[EE + warp];
    const float w = ew[warp];
    const float4* hs = reinterpret_cast<const float4*>(&g_h[src * OC]);
    float4* zd = reinterpret_cast<float4*>(&g_z[dst * OC]);
    #pragma unroll 2
    for (int c = lane; c < OC / 4; c += 32) {
        const float4 v = __ldg(hs + c);
        asm volatile("red.global.add.v4.f32 [%0], {%1, %2, %3, %4};"
                     :: "l"(zd + c), "f"(v.x * w), "f"(v.y * w), "f"(v.z * w), "f"(v.w * w)
                     : "memory");
    }
}

// ---------------------------------------------------------------------------
// mma.sync mainloop: 64x128 CTA tile, BK=64, 8 warps (2 row x 4 col),
// warp tile 32x32 (mi=2); plain fp16 single-MMA; 3-stage cp.async pipeline.
// ---------------------------------------------------------------------------
template<int NITER, int LAST_KS>
__device__ __forceinline__ void mma_mainloop(float acc[2][4][4], uint32_t sb,
    const __half* A, int arow0, int astride,
    const __half* B, int brow0, int bstride)
{
    const int wid = threadIdx.x >> 5;
    const int lane = threadIdx.x & 31;
    const int wrbase = (wid >> 2) * 32;   // warp row base (0 or 32)
    const int wcbase = (wid & 3) * 32;    // warp col base (0,32,64,96)

    const int a_row = wrbase + (lane & 15);
    const int a_kb  = (lane >> 4) * 16;
    const int b_row = wcbase + (lane & 7);
    const int b_kb  = ((lane >> 3) & 1) * 16;

    // prologue: fill stages 0 and 1
    fill_stage(sb + 0 * BUF_B, 0,  A, arow0, astride, B, brow0, bstride);
    CP_COMMIT();
    fill_stage(sb + 1 * BUF_B, 64, A, arow0, astride, B, brow0, bstride);
    CP_COMMIT();

    int st = 0;
    int fill_st = 2;
    #pragma unroll 1
    for (int iter = 0; iter < NITER; ++iter) {
        CP_WAIT(1);            // stage `st` complete (exactly 2 groups pending at entry)
        __syncthreads();       // all warps done reading the stage `fill_st` overwrites

        if (iter + 2 < NITER)
            fill_stage(sb + fill_st * BUF_B, (iter + 2) * 64,
                       A, arow0, astride, B, brow0, bstride);
        CP_COMMIT();           // always commit (possibly empty) to keep the count exact

        const uint32_t tA = sb + st * BUF_B + OFF_A;
        const uint32_t tB = sb + st * BUF_B + OFF_B;
        const int nks = (iter == NITER - 1) ? LAST_KS : 4;

        #pragma unroll
        for (int ks = 0; ks < 4; ks++) {
            if (ks >= nks) break;
            uint32_t a[2][4], b[4][2];
            #pragma unroll
            for (int mi = 0; mi < 2; mi++)
                ldsm_x4(a[mi], tile_addr(tA, a_row + mi * 16, ks * 32 + a_kb));
            #pragma unroll
            for (int ni = 0; ni < 4; ni++)
                ldsm_x2(b[ni], tile_addr(tB, b_row + ni * 8, ks * 32 + b_kb));
            #pragma unroll
            for (int mi = 0; mi < 2; mi++)
                #pragma unroll
                for (int ni = 0; ni < 4; ni++)
                    mma16816(acc[mi][ni], a[mi], b[ni]);
        }
        st = (st == NSTAGE - 1) ? 0 : st + 1;
        fill_st = (fill_st == NSTAGE - 1) ? 0 : fill_st + 1;
    }
}

// ---------------------------------------------------------------------------
// GEMM1: [g_h | g_z] (4096 x 400) = x @ [W_rel | W_root]    grid (4, 64)
// ---------------------------------------------------------------------------
__global__ __launch_bounds__(256, 2) void gemm1_mma(const float* __restrict__ b_rel) {
    extern __shared__ __align__(1024) char smem[];
    const uint32_t sb = smem_u32(smem);
    const int rowBase = blockIdx.y * 64;
    const int colBase = blockIdx.x * 128;

    float acc[2][4][4];
    #pragma unroll
    for (int i = 0; i < 2; i++)
        #pragma unroll
        for (int j = 0; j < 4; j++)
            #pragma unroll
            for (int t = 0; t < 4; t++) acc[i][j][t] = 0.f;

    mma_mainloop<NN / 64, 4>(acc, sb, g_xh, rowBase, NN, g_w1, colBase, NN);

    const int wid = threadIdx.x >> 5, lane = threadIdx.x & 31;
    const int wrbase = (wid >> 2) * 32, wcbase = (wid & 3) * 32;
    #pragma unroll
    for (int mi = 0; mi < 2; mi++) {
        #pragma unroll
        for (int ni = 0; ni < 4; ni++) {
            const int r0 = rowBase + wrbase + mi * 16 + (lane >> 2);
            const int gc = colBase + wcbase + ni * 8 + (lane & 3) * 2;
            #pragma unroll
            for (int h = 0; h < 2; h++) {
                const int r = r0 + h * 8;
                const float v0 = acc[mi][ni][h * 2 + 0];
                const float v1 = acc[mi][ni][h * 2 + 1];
                if (gc < OC) {
                    g_h[r * OC + gc] = v0;
                    g_h[r * OC + gc + 1] = v1;
                } else if (gc < 2 * OC) {
                    const int c = gc - OC;
                    g_z[r * OC + c] = v0 + __ldg(&b_rel[c]);
                    if (c + 1 < OC) g_z[r * OC + c + 1] = v1 + __ldg(&b_rel[c + 1]);
                }
            }
        }
    }
}

// ---------------------------------------------------------------------------
// GEMM2: out (4096 x 4096) = relu(z) @ W_dec + b_dec    grid (32, 64)
// Effective K = 208 (13 k16-steps): niter=4, last iteration 1 step.
// ---------------------------------------------------------------------------
__global__ __launch_bounds__(256, 2) void gemm2_mma(const float* __restrict__ b_dec,
                                                    float* __restrict__ out) {
    extern __shared__ __align__(1024) char smem[];
    const uint32_t sb = smem_u32(smem);
    const int rowBase = blockIdx.y * 64;
    const int colBase = blockIdx.x * 128;

    float acc[2][4][4];
    #pragma unroll
    for (int i = 0; i < 2; i++)
        #pragma unroll
        for (int j = 0; j < 4; j++)
            #pragma unroll
            for (int t = 0; t < 4; t++) acc[i][j][t] = 0.f;

    mma_mainloop<4, 1>(acc, sb, g_zh, rowBase, KPAD, g_wd, colBase, KPAD);

    const int wid = threadIdx.x >> 5, lane = threadIdx.x & 31;
    const int wrbase = (wid >> 2) * 32, wcbase = (wid & 3) * 32;
    #pragma unroll
    for (int mi = 0; mi < 2; mi++) {
        #pragma unroll
        for (int ni = 0; ni < 4; ni++) {
            const int r0 = rowBase + wrbase + mi * 16 + (lane >> 2);
            const int gc = colBase + wcbase + ni * 8 + (lane & 3) * 2;
            const float b0 = __ldg(&b_dec[gc]);
            const float b1 = __ldg(&b_dec[gc + 1]);
            #pragma unroll
            for (int h = 0; h < 2; h++) {
                const int r = r0 + h * 8;
                float2 o;
                o.x = acc[mi][ni][h * 2 + 0] + b0;
                o.y = acc[mi][ni][h * 2 + 1] + b1;
                *reinterpret_cast<float2*>(&out[(size_t)r * NN + gc]) = o;
            }
        }
    }
}

// ---------------------------------------------------------------------------
// Launch.  Inputs: x, edge_index, edge_weight, W_rel, b_rel, W_root, W_dec, b_dec
// ---------------------------------------------------------------------------
extern "C" void kernel_launch(void* const* d_in, const int* in_sizes, int n_in,
                              void* d_out, int out_size) {
    const float* x      = (const float*)d_in[0];
    const int*   ei     = (const int*)  d_in[1];
    const float* ew     = (const float*)d_in[2];
    const float* W_rel  = (const float*)d_in[3];
    const float* b_rel  = (const float*)d_in[4];
    const float* W_root = (const float*)d_in[5];
    const float* W_dec  = (const float*)d_in[6];
    const float* b_dec  = (const float*)d_in[7];
    float* out = (float*)d_out;

    cudaFuncSetAttribute(gemm1_mma, cudaFuncAttributeMaxDynamicSharedMemorySize, SMEM_TOTAL);
    cudaFuncSetAttribute(gemm2_mma, cudaFuncAttributeMaxDynamicSharedMemorySize, SMEM_TOTAL);

    conv_pre_kernel<<<28672, 256>>>(x, W_rel, W_root, W_dec);

    gemm1_mma<<<dim3(4, 64), 256, SMEM_TOTAL>>>(b_rel);
    scatter_kernel<<<8192, 256>>>(ei, ew);
    conv_z_kernel<<<512, 256>>>();
    gemm2_mma<<<dim3(32, 64), 256, SMEM_TOTAL>>>(b_dec, out);
}